// round 1
// baseline (speedup 1.0000x reference)
#include <cuda_runtime.h>

#define TT 4096
#define BB 256
#define KK 6
#define CC 64   // backtrack chunks
#define LL 64   // chunk length (CC*LL == TT)

// psi[t][b] packed as 8 bytes (byte j = argmax predecessor of state j at time t)
__device__ unsigned long long g_psi[(size_t)TT * BB];
__device__ int g_lastTag[BB];
__device__ unsigned int g_chunkMap[BB * CC];
__device__ int g_entryTag[BB * CC];

// ---------------------------------------------------------------------------
// Forward Viterbi: 6 compute lanes per chain (8-lane group), 4 chains/warp.
// Bit-exact replay of reference arithmetic:
//   s_k = fl(trans[t][j][k] + delta[k]);  m = max_k s_k (exact);
//   delta'[j] = fl(m + feat[t][j]);  psi = first k with s_k == m.
// ---------------------------------------------------------------------------
__global__ __launch_bounds__(32, 1) void fwd_kernel(const float* __restrict__ feats,
                                                    const float* __restrict__ trans,
                                                    float* __restrict__ out)
{
    const int lane = threadIdx.x;        // 0..31
    const int g    = lane >> 3;          // chain group within warp (0..3)
    const int j    = lane & 7;           // state row (0..5 active, 6..7 helpers)
    const int b    = blockIdx.x * 4 + g; // chain id
    const bool act = (j < 6);
    const int jj   = act ? j : 0;        // safe row for inactive lanes

    const float* tb = trans + (size_t)b * TT * (KK * KK) + jj * KK; // row ptr @ t=0
    const float* fb = feats + (size_t)b * TT * KK + jj;
    unsigned char* psip = (unsigned char*)g_psi + ((size_t)1 * BB + b) * 8 + jj;
    const int srcBase = g << 3;

    // delta init: -10000 everywhere except START_LABEL_ID=4 -> 0
    float d0 = -10000.0f, d1 = -10000.0f, d2 = -10000.0f,
          d3 = -10000.0f, d4 = 0.0f,     d5 = -10000.0f;

    const int P = 8;                     // register prefetch depth (steps)
    float2 bA[P], bB[P], bC[P];          // 6 trans row entries per step
    float  bF[P];                        // feat entry per step

#pragma unroll
    for (int i = 0; i < P; i++) {
        const float* p = tb + (size_t)(1 + i) * (KK * KK);
        bA[i] = __ldg((const float2*)p);
        bB[i] = __ldg((const float2*)(p + 2));
        bC[i] = __ldg((const float2*)(p + 4));
        bF[i] = __ldg(fb + (size_t)(1 + i) * KK);
    }

    for (int t0 = 1; t0 < TT; t0 += P) {
#pragma unroll
        for (int i = 0; i < P; i++) {
            int t = t0 + i;
            if (t >= TT) break;

            float s0 = bA[i].x + d0;
            float s1 = bA[i].y + d1;
            float s2 = bB[i].x + d2;
            float s3 = bB[i].y + d3;
            float s4 = bC[i].x + d4;
            float s5 = bC[i].y + d5;
            float ft = bF[i];

            // prefetch step t+P into the slot we just consumed
            int tn = t + P;
            if (tn < TT) {
                const float* p = tb + (size_t)tn * (KK * KK);
                bA[i] = __ldg((const float2*)p);
                bB[i] = __ldg((const float2*)(p + 2));
                bC[i] = __ldg((const float2*)(p + 4));
                bF[i] = __ldg(fb + (size_t)tn * KK);
            }

            // exact max (associative/commutative), tree for low latency
            float m01 = fmaxf(s0, s1);
            float m23 = fmaxf(s2, s3);
            float m45 = fmaxf(s4, s5);
            float m03 = fmaxf(m01, m23);
            float m   = fmaxf(m03, m45);

            // first-index argmax via equality (off critical path)
            int idx = (s0 == m) ? 0 :
                      (s1 == m) ? 1 :
                      (s2 == m) ? 2 :
                      (s3 == m) ? 3 :
                      (s4 == m) ? 4 : 5;

            float nd = m + ft;

            if (act) *psip = (unsigned char)idx;
            psip += BB * 8;

            // broadcast new deltas within the 6-lane group
            d0 = __shfl_sync(0xffffffffu, nd, srcBase + 0);
            d1 = __shfl_sync(0xffffffffu, nd, srcBase + 1);
            d2 = __shfl_sync(0xffffffffu, nd, srcBase + 2);
            d3 = __shfl_sync(0xffffffffu, nd, srcBase + 3);
            d4 = __shfl_sync(0xffffffffu, nd, srcBase + 4);
            d5 = __shfl_sync(0xffffffffu, nd, srcBase + 5);
        }
    }

    if (j == 0) {
        float m = d0; int idx = 0;
        if (d1 > m) { m = d1; idx = 1; }
        if (d2 > m) { m = d2; idx = 2; }
        if (d3 > m) { m = d3; idx = 3; }
        if (d4 > m) { m = d4; idx = 4; }
        if (d5 > m) { m = d5; idx = 5; }
        out[b] = m;          // score
        g_lastTag[b] = idx;  // start of backtrack
    }
}

// ---------------------------------------------------------------------------
// Backtrack pass A: per (b, chunk) compose the backward map
//   M_c = g_{cL} o ... o g_{(c+1)L-1},  g_t(x) = psi[t+1][b][x],  g_{T-1} = id
// ---------------------------------------------------------------------------
__global__ void bt_chunk_kernel()
{
    int tid = blockIdx.x * blockDim.x + threadIdx.x; // 0 .. BB*CC-1
    int b = tid >> 6;
    int c = tid & (CC - 1);
    int m0 = 0, m1 = 1, m2 = 2, m3 = 3, m4 = 4, m5 = 5;
    int tLo = c * LL;
#pragma unroll 4
    for (int t = tLo + LL - 1; t >= tLo; t--) {
        if (t == TT - 1) continue; // identity
        unsigned long long w = __ldg(&g_psi[(size_t)(t + 1) * BB + b]);
        m0 = (int)((w >> (m0 << 3)) & 7ull);
        m1 = (int)((w >> (m1 << 3)) & 7ull);
        m2 = (int)((w >> (m2 << 3)) & 7ull);
        m3 = (int)((w >> (m3 << 3)) & 7ull);
        m4 = (int)((w >> (m4 << 3)) & 7ull);
        m5 = (int)((w >> (m5 << 3)) & 7ull);
    }
    g_chunkMap[b * CC + c] = (unsigned)(m0 | (m1 << 4) | (m2 << 8) |
                                        (m3 << 12) | (m4 << 16) | (m5 << 20));
}

// ---------------------------------------------------------------------------
// Backtrack pass B: per chain, sequential scan across the CC chunk maps.
// entryTag[b][c] = tag at position (c+1)*LL (with tag_T := last_tag).
// ---------------------------------------------------------------------------
__global__ void bt_scan_kernel()
{
    int b = threadIdx.x;
    int x = g_lastTag[b];
#pragma unroll 4
    for (int c = CC - 1; c >= 0; c--) {
        g_entryTag[b * CC + c] = x;
        unsigned w = g_chunkMap[b * CC + c];
        x = (int)((w >> (x << 2)) & 7u);
    }
}

// ---------------------------------------------------------------------------
// Backtrack pass C: per (b, chunk) emit path entries.
// ---------------------------------------------------------------------------
__global__ void bt_emit_kernel(float* __restrict__ out)
{
    int tid = blockIdx.x * blockDim.x + threadIdx.x;
    int b = tid >> 6;
    int c = tid & (CC - 1);
    int x = g_entryTag[b * CC + c];
    float* pout = out + BB + (size_t)b * TT; // path block, after 256 scores
    int tLo = c * LL;
#pragma unroll 4
    for (int t = tLo + LL - 1; t >= tLo; t--) {
        if (t != TT - 1) {
            unsigned long long w = __ldg(&g_psi[(size_t)(t + 1) * BB + b]);
            x = (int)((w >> (x << 3)) & 7ull);
        }
        pout[t] = (float)x;
    }
}

// ---------------------------------------------------------------------------
extern "C" void kernel_launch(void* const* d_in, const int* in_sizes, int n_in,
                              void* d_out, int out_size)
{
    const float* feats = (const float*)d_in[0];
    const float* trans = (const float*)d_in[1];
    // defensive: feats is the smaller tensor
    if (n_in >= 2 && in_sizes[0] > in_sizes[1]) {
        const float* tmp = feats; feats = trans; trans = tmp;
    }
    float* out = (float*)d_out;

    fwd_kernel<<<BB / 4, 32>>>(feats, trans, out);
    bt_chunk_kernel<<<(BB * CC) / 256, 256>>>();
    bt_scan_kernel<<<1, BB>>>();
    bt_emit_kernel<<<(BB * CC) / 256, 256>>>(out);
}

// round 2
// speedup vs baseline: 3.5534x; 3.5534x over previous
#include <cuda_runtime.h>

#define TT 4096
#define BB 256
#define KK 6
#define CC 64   // backtrack chunks
#define LL 64   // chunk length (CC*LL == TT)
#define PF 15   // prefetch depth; (TT-1) = 4095 = 273 * 15 exactly

// psi[t][b] packed as 8 bytes (byte j = argmax predecessor of state j at time t)
__device__ unsigned long long g_psi[(size_t)TT * BB];
__device__ int g_lastTag[BB];
__device__ unsigned int g_chunkMap[BB * CC];
__device__ int g_entryTag[BB * CC];

// ---------------------------------------------------------------------------
// Forward Viterbi: 6 compute lanes per chain (8-lane group), 4 chains/warp.
// Bit-exact replay of reference arithmetic:
//   s_k = fl(trans[t][j][k] + delta[k]);  m = max_k s_k (exact);
//   delta'[j] = fl(m + feat[t][j]);  psi = first k with s_k == m.
// Fully static unroll (no break) so the PF-deep prefetch ring stays in regs.
// ---------------------------------------------------------------------------
__global__ __launch_bounds__(32, 1) void fwd_kernel(const float* __restrict__ feats,
                                                    const float* __restrict__ trans,
                                                    float* __restrict__ out)
{
    const int lane = threadIdx.x;        // 0..31
    const int g    = lane >> 3;          // chain group within warp (0..3)
    const int j    = lane & 7;           // state row (0..5 active, 6..7 helpers)
    const int b    = blockIdx.x * 4 + g; // chain id
    const bool act = (j < 6);
    const int jj   = act ? j : 0;        // safe row for inactive lanes

    // byte base pointers; per-step strides: trans row 144 B, feats 24 B, psi 2048 B
    const char* tbase = (const char*)(trans + (size_t)b * TT * (KK * KK) + jj * KK);
    const char* fbase = (const char*)(feats + (size_t)b * TT * KK + jj);
    char* pbase = (char*)g_psi + (size_t)b * 8 + jj;
    const int srcBase = g << 3;

    // delta init: -10000 everywhere except START_LABEL_ID=4 -> 0
    float d0 = -10000.0f, d1 = -10000.0f, d2 = -10000.0f,
          d3 = -10000.0f, d4 = 0.0f,     d5 = -10000.0f;

    float2 bA[PF], bB[PF], bC[PF];       // 6 trans row entries per slot
    float  bF[PF];                       // feat entry per slot

    // initial prefetch: steps t = 1 .. PF
#pragma unroll
    for (int i = 0; i < PF; i++) {
        const char* p = tbase + (size_t)(1 + i) * 144;
        bA[i] = __ldg((const float2*)p);
        bB[i] = __ldg((const float2*)(p + 8));
        bC[i] = __ldg((const float2*)(p + 16));
        bF[i] = __ldg((const float*)(fbase + (size_t)(1 + i) * 24));
    }

    // rolling byte offsets (updated once per outer iteration)
    size_t tOff = (size_t)(1 + PF) * 144;   // next trans row to prefetch
    size_t fOff = (size_t)(1 + PF) * 24;    // next feat to prefetch
    size_t pOff = (size_t)1 * 2048;         // psi row for current step

    for (int t0 = 1; t0 < TT; t0 += PF) {
#pragma unroll
        for (int i = 0; i < PF; i++) {
            float s0 = bA[i].x + d0;
            float s1 = bA[i].y + d1;
            float s2 = bB[i].x + d2;
            float s3 = bB[i].y + d3;
            float s4 = bC[i].x + d4;
            float s5 = bC[i].y + d5;
            float ft = bF[i];

            // prefetch step (t0+i)+PF into the slot just consumed (predicated off at tail)
            if (t0 + i + PF < TT) {
                const char* p = tbase + tOff + (size_t)i * 144;
                bA[i] = __ldg((const float2*)p);
                bB[i] = __ldg((const float2*)(p + 8));
                bC[i] = __ldg((const float2*)(p + 16));
                bF[i] = __ldg((const float*)(fbase + fOff + (size_t)i * 24));
            }

            // exact max (associative/commutative), tree for low latency
            float m01 = fmaxf(s0, s1);
            float m23 = fmaxf(s2, s3);
            float m45 = fmaxf(s4, s5);
            float m03 = fmaxf(m01, m23);
            float m   = fmaxf(m03, m45);

            // first-index argmax via equality (off critical path)
            int idx = (s0 == m) ? 0 :
                      (s1 == m) ? 1 :
                      (s2 == m) ? 2 :
                      (s3 == m) ? 3 :
                      (s4 == m) ? 4 : 5;

            float nd = m + ft;

            if (act) *(unsigned char*)(pbase + pOff + (size_t)i * 2048) = (unsigned char)idx;

            // broadcast new deltas within the 6-lane group
            d0 = __shfl_sync(0xffffffffu, nd, srcBase + 0);
            d1 = __shfl_sync(0xffffffffu, nd, srcBase + 1);
            d2 = __shfl_sync(0xffffffffu, nd, srcBase + 2);
            d3 = __shfl_sync(0xffffffffu, nd, srcBase + 3);
            d4 = __shfl_sync(0xffffffffu, nd, srcBase + 4);
            d5 = __shfl_sync(0xffffffffu, nd, srcBase + 5);
        }
        tOff += (size_t)PF * 144;
        fOff += (size_t)PF * 24;
        pOff += (size_t)PF * 2048;
    }

    if (j == 0) {
        float m = d0; int idx = 0;
        if (d1 > m) { m = d1; idx = 1; }
        if (d2 > m) { m = d2; idx = 2; }
        if (d3 > m) { m = d3; idx = 3; }
        if (d4 > m) { m = d4; idx = 4; }
        if (d5 > m) { m = d5; idx = 5; }
        out[b] = m;          // score
        g_lastTag[b] = idx;  // start of backtrack
    }
}

// ---------------------------------------------------------------------------
// Backtrack pass A: per (b, chunk) compose the backward map
//   M_c = g_{cL} o ... o g_{(c+1)L-1},  g_t(x) = psi[t+1][b][x],  g_{T-1} = id
// ---------------------------------------------------------------------------
__global__ void bt_chunk_kernel()
{
    int tid = blockIdx.x * blockDim.x + threadIdx.x; // 0 .. BB*CC-1
    int b = tid >> 6;
    int c = tid & (CC - 1);
    int m0 = 0, m1 = 1, m2 = 2, m3 = 3, m4 = 4, m5 = 5;
    int tLo = c * LL;
#pragma unroll 4
    for (int t = tLo + LL - 1; t >= tLo; t--) {
        if (t == TT - 1) continue; // identity
        unsigned long long w = __ldg(&g_psi[(size_t)(t + 1) * BB + b]);
        m0 = (int)((w >> (m0 << 3)) & 7ull);
        m1 = (int)((w >> (m1 << 3)) & 7ull);
        m2 = (int)((w >> (m2 << 3)) & 7ull);
        m3 = (int)((w >> (m3 << 3)) & 7ull);
        m4 = (int)((w >> (m4 << 3)) & 7ull);
        m5 = (int)((w >> (m5 << 3)) & 7ull);
    }
    g_chunkMap[b * CC + c] = (unsigned)(m0 | (m1 << 4) | (m2 << 8) |
                                        (m3 << 12) | (m4 << 16) | (m5 << 20));
}

// ---------------------------------------------------------------------------
// Backtrack pass B: per chain, sequential scan across the CC chunk maps.
// entryTag[b][c] = tag at position (c+1)*LL (with tag_T := last_tag).
// ---------------------------------------------------------------------------
__global__ void bt_scan_kernel()
{
    int b = threadIdx.x;
    int x = g_lastTag[b];
#pragma unroll 4
    for (int c = CC - 1; c >= 0; c--) {
        g_entryTag[b * CC + c] = x;
        unsigned w = g_chunkMap[b * CC + c];
        x = (int)((w >> (x << 2)) & 7u);
    }
}

// ---------------------------------------------------------------------------
// Backtrack pass C: per (b, chunk) emit path entries.
// ---------------------------------------------------------------------------
__global__ void bt_emit_kernel(float* __restrict__ out)
{
    int tid = blockIdx.x * blockDim.x + threadIdx.x;
    int b = tid >> 6;
    int c = tid & (CC - 1);
    int x = g_entryTag[b * CC + c];
    float* pout = out + BB + (size_t)b * TT; // path block, after 256 scores
    int tLo = c * LL;
#pragma unroll 4
    for (int t = tLo + LL - 1; t >= tLo; t--) {
        if (t != TT - 1) {
            unsigned long long w = __ldg(&g_psi[(size_t)(t + 1) * BB + b]);
            x = (int)((w >> (x << 3)) & 7ull);
        }
        pout[t] = (float)x;
    }
}

// ---------------------------------------------------------------------------
extern "C" void kernel_launch(void* const* d_in, const int* in_sizes, int n_in,
                              void* d_out, int out_size)
{
    const float* feats = (const float*)d_in[0];
    const float* trans = (const float*)d_in[1];
    // defensive: feats is the smaller tensor
    if (n_in >= 2 && in_sizes[0] > in_sizes[1]) {
        const float* tmp = feats; feats = trans; trans = tmp;
    }
    float* out = (float*)d_out;

    fwd_kernel<<<BB / 4, 32>>>(feats, trans, out);
    bt_chunk_kernel<<<(BB * CC) / 256, 256>>>();
    bt_scan_kernel<<<1, BB>>>();
    bt_emit_kernel<<<(BB * CC) / 256, 256>>>(out);
}